// round 15
// baseline (speedup 1.0000x reference)
#include <cuda_runtime.h>
#include <cstdint>
#include <math.h>

#define NTOK 16384
#define DM 512
#define DH 2048
#define NE 8
#define NASN (2*NTOK)          // 32768 assignments
#define CAP (NASN + NE*128)    // 33792 (each expert padded to 128)
#define NTILES (CAP/128)       // 264 row tiles

// ---- scratch (device globals; fp16 data held in uint32_t arrays ONLY) ----
__device__ int      g_cnt[NE];
__device__ int      g_off[NE+1];
__device__ int      g_tile_e[NTILES];
__device__ int      g_as_e[NASN];
__device__ int      g_as_r[NASN];
__device__ float    g_as_w[NASN];
__device__ int      g_tokpos[NASN];
__device__ int      g_extok[CAP];
__device__ uint32_t g_xp[(size_t)NTOK*(DM/2)];      // x as f16 pairs: [t][kp=256]
__device__ uint32_t g_w1p[(size_t)NE*(DM/2)*DH];    // W1 pairs: [e][kp=256][n=2048]
__device__ uint32_t g_w2p[(size_t)NE*(DH/2)*DM];    // W2 pairs: [e][kp=1024][n=512]
__device__ uint32_t g_hp[(size_t)CAP*(DH/2)];       // hidden f16 pairs: [row][kp=1024]
__device__ float    g_ybuf[(size_t)CAP*DM];

// ---- helpers ----
__device__ __forceinline__ uint32_t pk(float lo, float hi){
    uint32_t r; asm("cvt.rn.f16x2.f32 %0, %1, %2;" : "=r"(r) : "f"(hi), "f"(lo));
    return r;
}
__device__ __forceinline__ void mma16(float* c, const uint32_t* a, const uint32_t* b){
    asm volatile(
      "mma.sync.aligned.m16n8k16.row.col.f32.f16.f16.f32 "
      "{%0,%1,%2,%3},{%4,%5,%6,%7},{%8,%9},{%0,%1,%2,%3};"
      : "+f"(c[0]), "+f"(c[1]), "+f"(c[2]), "+f"(c[3])
      : "r"(a[0]), "r"(a[1]), "r"(a[2]), "r"(a[3]), "r"(b[0]), "r"(b[1]));
}
__device__ __forceinline__ float gelu_exact(float x){
    return 0.5f * x * (1.0f + erff(x * 0.7071067811865476f));
}

// ---- launch 1: init + pair-pack W1,W2 to fp16 (u32 arrays) ----
__global__ void k_initcvt(const float* __restrict__ W1, const float* __restrict__ W2){
    int i = blockIdx.x * 256 + threadIdx.x;   // 0 .. 1048575
    if (i < NE) g_cnt[i] = 0;
    if (i < CAP) g_extok[i] = -1;
    // W1: K=512, N=2048 -> kp = i>>9, n4 = i&511
    {
        int n4 = i & 511, kp = i >> 9;
        const float* r0 = W1 + (size_t)(2*kp) * 2048 + n4*4;
        float4 lo = *(const float4*)r0;
        float4 hi = *(const float4*)(r0 + 2048);
        uint4 o;
        o.x = pk(lo.x, hi.x); o.y = pk(lo.y, hi.y);
        o.z = pk(lo.z, hi.z); o.w = pk(lo.w, hi.w);
        ((uint4*)g_w1p)[(size_t)kp * 512 + n4] = o;
    }
    // W2: K=2048, N=512 -> kp = i>>7, n4 = i&127
    {
        int n4 = i & 127, kp = i >> 7;
        const float* r0 = W2 + (size_t)(2*kp) * 512 + n4*4;
        float4 lo = *(const float4*)r0;
        float4 hi = *(const float4*)(r0 + 512);
        uint4 o;
        o.x = pk(lo.x, hi.x); o.y = pk(lo.y, hi.y);
        o.z = pk(lo.z, hi.z); o.w = pk(lo.w, hi.w);
        ((uint4*)g_w2p)[(size_t)kp * 128 + n4] = o;
    }
}

// ---- launch 2: router + x->f16 pair conversion (fused) ----
__global__ void k_router(const float* __restrict__ x, const float* __restrict__ Wg,
                         float* __restrict__ out_logits){
    {
        int base = blockIdx.x * 512;
        #pragma unroll
        for (int k = 0; k < 2; k++){
            int j = base + threadIdx.x + k*256;
            float4 v0 = ((const float4*)x)[2*j];
            float4 v1 = ((const float4*)x)[2*j + 1];
            uint4 u;
            u.x = pk(v0.x, v0.y); u.y = pk(v0.z, v0.w);
            u.z = pk(v1.x, v1.y); u.w = pk(v1.z, v1.w);
            ((uint4*)g_xp)[j] = u;
        }
    }
    __shared__ float sWg[NE*DM];
    for (int i = threadIdx.x; i < NE*DM; i += 256) sWg[i] = Wg[i];
    __syncthreads();
    int wid = threadIdx.x >> 5, lane = threadIdx.x & 31;
    int t = blockIdx.x * 8 + wid;
    const float* xr = x + (size_t)t * DM;
    float acc[NE];
    #pragma unroll
    for (int e = 0; e < NE; e++) acc[e] = 0.f;
    for (int i = lane; i < DM; i += 32){
        float xv = xr[i];
        #pragma unroll
        for (int e = 0; e < NE; e++) acc[e] += xv * sWg[e*DM + i];
    }
    #pragma unroll
    for (int e = 0; e < NE; e++){
        float v = acc[e];
        #pragma unroll
        for (int o = 16; o > 0; o >>= 1) v += __shfl_xor_sync(0xffffffffu, v, o);
        acc[e] = v;
    }
    if (lane == 0){
        #pragma unroll
        for (int e = 0; e < NE; e++) out_logits[(size_t)t*NE + e] = acc[e];
        int e0 = 0; float v0 = acc[0];
        #pragma unroll
        for (int e = 1; e < NE; e++) if (acc[e] > v0){ v0 = acc[e]; e0 = e; }
        int e1 = -1; float v1 = -3.4e38f;
        #pragma unroll
        for (int e = 0; e < NE; e++) if (e != e0 && acc[e] > v1){ v1 = acc[e]; e1 = e; }
        float ex = expf(v1 - v0);
        float s  = 1.0f + ex;
        float w0 = 1.0f / s, w1 = ex / s;
        int r0 = atomicAdd(&g_cnt[e0], 1);
        int r1 = atomicAdd(&g_cnt[e1], 1);
        g_as_e[2*t] = e0;   g_as_r[2*t] = r0;   g_as_w[2*t] = w0;
        g_as_e[2*t+1] = e1; g_as_r[2*t+1] = r1; g_as_w[2*t+1] = w1;
    }
}

// ---- launch 3: offsets + tile map + scatter (single block) ----
__global__ void k_offscat(){
    __shared__ int soff[NE+1];
    if (threadIdx.x == 0){
        int o = 0; soff[0] = 0;
        for (int e = 0; e < NE; e++){ o += (g_cnt[e] + 127) & ~127; soff[e+1] = o; }
    }
    __syncthreads();
    for (int i = threadIdx.x; i < NTILES; i += blockDim.x){
        int pos = i * 128, te = -1;
        for (int e = 0; e < NE; e++)
            if (pos >= soff[e] && pos < soff[e+1]) te = e;
        g_tile_e[i] = te;
    }
    if (threadIdx.x <= NE) g_off[threadIdx.x] = soff[threadIdx.x];
    for (int i = threadIdx.x; i < NASN; i += blockDim.x){
        int e = g_as_e[i];
        int pos = soff[e] + g_as_r[i];
        g_extok[pos] = i >> 1;
        g_tokpos[i] = pos;
    }
}

// ---- launches 4/5: pipelined fp16 GEMM, 256 thr / 8 warps of 64x32 ----
// Block 128x128, BK=64 halves (32 u32 pair-cols), 3-stage cp.async (96KB), 2 CTAs/SM.
// FIRST: A = gather g_xp rows (K=512h), B = g_w1p, C = g_hp (gelu->f16 pairs)
// !FIRST: A = g_hp rows (K=2048h),      B = g_w2p, C = g_ybuf (fp32)
template<bool FIRST>
__global__ __launch_bounds__(256, 2)
void k_gemm(){
    constexpr int KP  = FIRST ? (DM/2) : (DH/2);   // A row stride in u32 pairs
    constexpr int NT  = FIRST ? DH : DM;
    constexpr int NIT = FIRST ? (DM/64) : (DH/64); // 8 / 32 iters
    extern __shared__ uint32_t smem[];   // A: 3*4096 u32, B: 3*4096 u32 (96KB)
    int tile = blockIdx.y;
    int e = g_tile_e[tile];
    if (e < 0) return;
    int n0 = blockIdx.x * 128;
    int tid = threadIdx.x, lane = tid & 31, wid = tid >> 5;
    int g = lane >> 2, t4 = lane & 3;
    int wm = wid & 1, wn = wid >> 1;       // 2 x 4 warp grid, warp tile 64x32
    uint32_t smem_b;
    asm("{ .reg .u64 t; cvta.to.shared.u64 t, %1; cvt.u32.u64 %0, t; }"
        : "=r"(smem_b) : "l"(smem));

    const uint32_t* __restrict__ Wp = (FIRST ? g_w1p : g_w2p) + (size_t)e * KP * NT;
    const uint32_t* __restrict__ Ab = FIRST ? g_xp : (g_hp + (size_t)tile * 128 * KP);

    int tokr[4];
    if (FIRST){
        #pragma unroll
        for (int i = 0; i < 4; i++)
            tokr[i] = g_extok[tile*128 + (tid >> 3) + i*32];
    }
    int rA0 = tid >> 3, jA = tid & 7;     // A staging: row (0..31), 16B-chunk
    int rB0 = tid >> 5, cB = tid & 31;    // B staging: pair-row (0..7), 16B-chunk

    // stage `idx` covers pair-cols [idx*32, idx*32+32)
    auto issue = [&](int s, int idx){
        uint32_t ab = smem_b + s * 16384;
        uint32_t bb = smem_b + 49152 + s * 16384;
        int kp = idx * 32;
        #pragma unroll
        for (int i = 0; i < 4; i++){
            int r = rA0 + i*32;
            uint32_t dst = ab + ((r*32 + ((jA ^ (r & 7)) << 2)) << 2);
            const uint32_t* src; int sz = 16;
            if (FIRST){
                int tok = tokr[i];
                src = Ab + (size_t)(tok < 0 ? 0 : tok) * KP + kp + (jA << 2);
                sz = (tok < 0) ? 0 : 16;
            } else {
                src = Ab + (size_t)r * KP + kp + (jA << 2);
            }
            asm volatile("cp.async.cg.shared.global [%0], [%1], 16, %2;"
                         :: "r"(dst), "l"(src), "r"(sz));
        }
        #pragma unroll
        for (int i = 0; i < 4; i++){
            int r = rB0 + i*8;
            uint32_t dst = bb + ((r*128 + ((cB ^ ((r & 3) << 1)) << 2)) << 2);
            const uint32_t* src = Wp + (size_t)(kp + r) * NT + n0 + (cB << 2);
            asm volatile("cp.async.cg.shared.global [%0], [%1], 16, %2;"
                         :: "r"(dst), "l"(src), "r"(16));
        }
    };

    float acc[4][4][4];
    #pragma unroll
    for (int im = 0; im < 4; im++)
        #pragma unroll
        for (int jn = 0; jn < 4; jn++)
            #pragma unroll
            for (int q = 0; q < 4; q++) acc[im][jn][q] = 0.f;

    issue(0, 0); asm volatile("cp.async.commit_group;" ::: "memory");
    issue(1, 1); asm volatile("cp.async.commit_group;" ::: "memory");

    int bco[4];
    #pragma unroll
    for (int jn = 0; jn < 4; jn++){
        int c = wn*32 + jn*8 + g;
        bco[jn] = (((c >> 2) ^ (t4 << 1)) << 2) + (c & 3);
    }

    for (int it = 0; it < NIT; ++it){
        asm volatile("cp.async.wait_group 1;" ::: "memory");
        __syncthreads();
        if (it + 2 < NIT) issue((it + 2) % 3, it + 2);
        asm volatile("cp.async.commit_group;" ::: "memory");
        const uint32_t* sa = smem + (it % 3) * 4096;
        const uint32_t* sb = smem + 12288 + (it % 3) * 4096;
        #pragma unroll
        for (int ks = 0; ks < 4; ks++){
            int kk = ks * 8;
            int ka = kk + t4;               // u32 pair-col of A frag reg0
            int w  = ka & 3;
            int c0 = ka >> 2, c1 = c0 + 1;
            uint32_t a[4][4];
            #pragma unroll
            for (int im = 0; im < 4; im++){
                int r0 = wm*64 + im*16 + g;
                const uint32_t* p0 = sa + r0*32;
                const uint32_t* p1 = p0 + 256;         // +8 rows, same (row&7)
                a[im][0] = p0[((c0 ^ g) << 2) + w];
                a[im][1] = p1[((c0 ^ g) << 2) + w];
                a[im][2] = p0[((c1 ^ g) << 2) + w];
                a[im][3] = p1[((c1 ^ g) << 2) + w];
            }
            uint32_t b[4][2];
            const uint32_t* sbr = sb + (kk + t4) * 128;
            #pragma unroll
            for (int jn = 0; jn < 4; jn++){
                b[jn][0] = sbr[bco[jn]];
                b[jn][1] = sbr[bco[jn] + 512];          // +4 pair-rows (= +8 halves)
            }
            #pragma unroll
            for (int im = 0; im < 4; im++)
                #pragma unroll
                for (int jn = 0; jn < 4; jn++)
                    mma16(acc[im][jn], a[im], b[jn]);
        }
    }

    // epilogue
    #pragma unroll
    for (int im = 0; im < 4; im++){
        int r = wm*64 + im*16 + g;
        #pragma unroll
        for (int jn = 0; jn < 4; jn++){
            int c = n0 + wn*32 + jn*8 + (t4 << 1);   // even
            if (FIRST){
                uint32_t* Ch = g_hp + (size_t)tile * 128 * (DH/2);
                int cp = c >> 1;
                Ch[(size_t)r * (DH/2) + cp] =
                    pk(gelu_exact(acc[im][jn][0]), gelu_exact(acc[im][jn][1]));
                Ch[(size_t)(r + 8) * (DH/2) + cp] =
                    pk(gelu_exact(acc[im][jn][2]), gelu_exact(acc[im][jn][3]));
            } else {
                float* Cf = g_ybuf + (size_t)tile * 128 * DM;
                *(float2*)(Cf + (size_t)r * DM + c)       = make_float2(acc[im][jn][0], acc[im][jn][1]);
                *(float2*)(Cf + (size_t)(r + 8) * DM + c) = make_float2(acc[im][jn][2], acc[im][jn][3]);
            }
        }
    }
}

// ---- launch 6: combine ----
__global__ void k_combine(float* __restrict__ out){
    int idx = blockIdx.x * 256 + threadIdx.x;
    int t = idx >> 7, d4 = idx & 127;
    int p0 = g_tokpos[2*t], p1 = g_tokpos[2*t + 1];
    float w0 = g_as_w[2*t], w1 = g_as_w[2*t + 1];
    float4 y0 = *(const float4*)(g_ybuf + (size_t)p0*DM + d4*4);
    float4 y1 = *(const float4*)(g_ybuf + (size_t)p1*DM + d4*4);
    float4 o;
    o.x = w0*y0.x + w1*y1.x;
    o.y = w0*y0.y + w1*y1.y;
    o.z = w0*y0.z + w1*y1.z;
    o.w = w0*y0.w + w1*y1.w;
    *(float4*)(out + (size_t)t*DM + d4*4) = o;
}

extern "C" void kernel_launch(void* const* d_in, const int* in_sizes, int n_in,
                              void* d_out, int out_size){
    const float* x  = (const float*)d_in[0];   // [16384, 512]
    const float* Wg = (const float*)d_in[1];   // [8, 512]
    const float* W1 = (const float*)d_in[2];   // [8, 512, 2048]
    const float* W2 = (const float*)d_in[3];   // [8, 2048, 512]
    float* out = (float*)d_out;                // out [T,512] then logits [T,8]

    const int SMEM = 98304;
    cudaFuncSetAttribute(k_gemm<true>,  cudaFuncAttributeMaxDynamicSharedMemorySize, SMEM);
    cudaFuncSetAttribute(k_gemm<false>, cudaFuncAttributeMaxDynamicSharedMemorySize, SMEM);

    k_initcvt<<<4096, 256>>>(W1, W2);                        // launch 1
    k_router<<<NTOK/8, 256>>>(x, Wg, out + (size_t)NTOK*DM); // launch 2 (+x cvt)
    k_offscat<<<1, 1024>>>();                                // launch 3
    k_gemm<true><<<dim3(DH/128, NTILES), 256, SMEM>>>();     // launch 4 <- ncu lands here
    k_gemm<false><<<dim3(DM/128, NTILES), 256, SMEM>>>();    // launch 5
    k_combine<<<(NTOK*128)/256, 256>>>(out);                 // launch 6
}

// round 16
// speedup vs baseline: 1.0484x; 1.0484x over previous
#include <cuda_runtime.h>
#include <cstdint>
#include <math.h>

#define NTOK 16384
#define DM 512
#define DH 2048
#define NE 8
#define NASN (2*NTOK)          // 32768 assignments
#define CAP (NASN + NE*128)    // 33792 (each expert padded to 128)
#define NTILES (CAP/128)       // 264 row tiles

// ---- scratch (device globals; fp16 data held in uint32_t arrays ONLY) ----
__device__ int      g_cnt[NE];
__device__ int      g_off[NE+1];
__device__ int      g_tile_e[NTILES];
__device__ int      g_as_e[NASN];
__device__ int      g_as_r[NASN];
__device__ float    g_as_w[NASN];
__device__ int      g_tokpos[NASN];
__device__ int      g_extok[CAP];
__device__ uint32_t g_xp[(size_t)NTOK*(DM/2)];      // x as f16 pairs: [t][kp=256]
__device__ uint32_t g_w1p[(size_t)NE*(DM/2)*DH];    // W1 pairs: [e][kp=256][n=2048]
__device__ uint32_t g_w2p[(size_t)NE*(DH/2)*DM];    // W2 pairs: [e][kp=1024][n=512]
__device__ uint32_t g_hp[(size_t)CAP*(DH/2)];       // hidden f16 pairs: [row][kp=1024]
__device__ float    g_ybuf[(size_t)CAP*DM];

// ---- helpers ----
__device__ __forceinline__ uint32_t pk(float lo, float hi){
    uint32_t r; asm("cvt.rn.f16x2.f32 %0, %1, %2;" : "=r"(r) : "f"(hi), "f"(lo));
    return r;
}
__device__ __forceinline__ void mma16(float* c, const uint32_t* a, const uint32_t* b){
    asm volatile(
      "mma.sync.aligned.m16n8k16.row.col.f32.f16.f16.f32 "
      "{%0,%1,%2,%3},{%4,%5,%6,%7},{%8,%9},{%0,%1,%2,%3};"
      : "+f"(c[0]), "+f"(c[1]), "+f"(c[2]), "+f"(c[3])
      : "r"(a[0]), "r"(a[1]), "r"(a[2]), "r"(a[3]), "r"(b[0]), "r"(b[1]));
}
__device__ __forceinline__ void ldsm4(uint32_t* r, uint32_t addr){
    asm volatile("ldmatrix.sync.aligned.m8n8.x4.shared.b16 {%0,%1,%2,%3}, [%4];"
        : "=r"(r[0]), "=r"(r[1]), "=r"(r[2]), "=r"(r[3]) : "r"(addr));
}
__device__ __forceinline__ float gelu_exact(float x){
    return 0.5f * x * (1.0f + erff(x * 0.7071067811865476f));
}

// ---- launch 1: init + pair-pack W1,W2 to fp16 (u32 arrays) ----
__global__ void k_initcvt(const float* __restrict__ W1, const float* __restrict__ W2){
    int i = blockIdx.x * 256 + threadIdx.x;   // 0 .. 1048575
    if (i < NE) g_cnt[i] = 0;
    if (i < CAP) g_extok[i] = -1;
    // W1: K=512, N=2048 -> kp = i>>9, n4 = i&511
    {
        int n4 = i & 511, kp = i >> 9;
        const float* r0 = W1 + (size_t)(2*kp) * 2048 + n4*4;
        float4 lo = *(const float4*)r0;
        float4 hi = *(const float4*)(r0 + 2048);
        uint4 o;
        o.x = pk(lo.x, hi.x); o.y = pk(lo.y, hi.y);
        o.z = pk(lo.z, hi.z); o.w = pk(lo.w, hi.w);
        ((uint4*)g_w1p)[(size_t)kp * 512 + n4] = o;
    }
    // W2: K=2048, N=512 -> kp = i>>7, n4 = i&127
    {
        int n4 = i & 127, kp = i >> 7;
        const float* r0 = W2 + (size_t)(2*kp) * 512 + n4*4;
        float4 lo = *(const float4*)r0;
        float4 hi = *(const float4*)(r0 + 512);
        uint4 o;
        o.x = pk(lo.x, hi.x); o.y = pk(lo.y, hi.y);
        o.z = pk(lo.z, hi.z); o.w = pk(lo.w, hi.w);
        ((uint4*)g_w2p)[(size_t)kp * 128 + n4] = o;
    }
}

// ---- launch 2: router + x->f16 pair conversion (fused) ----
__global__ void k_router(const float* __restrict__ x, const float* __restrict__ Wg,
                         float* __restrict__ out_logits){
    {
        int base = blockIdx.x * 512;
        #pragma unroll
        for (int k = 0; k < 2; k++){
            int j = base + threadIdx.x + k*256;
            float4 v0 = ((const float4*)x)[2*j];
            float4 v1 = ((const float4*)x)[2*j + 1];
            uint4 u;
            u.x = pk(v0.x, v0.y); u.y = pk(v0.z, v0.w);
            u.z = pk(v1.x, v1.y); u.w = pk(v1.z, v1.w);
            ((uint4*)g_xp)[j] = u;
        }
    }
    __shared__ float sWg[NE*DM];
    for (int i = threadIdx.x; i < NE*DM; i += 256) sWg[i] = Wg[i];
    __syncthreads();
    int wid = threadIdx.x >> 5, lane = threadIdx.x & 31;
    int t = blockIdx.x * 8 + wid;
    const float* xr = x + (size_t)t * DM;
    float acc[NE];
    #pragma unroll
    for (int e = 0; e < NE; e++) acc[e] = 0.f;
    for (int i = lane; i < DM; i += 32){
        float xv = xr[i];
        #pragma unroll
        for (int e = 0; e < NE; e++) acc[e] += xv * sWg[e*DM + i];
    }
    #pragma unroll
    for (int e = 0; e < NE; e++){
        float v = acc[e];
        #pragma unroll
        for (int o = 16; o > 0; o >>= 1) v += __shfl_xor_sync(0xffffffffu, v, o);
        acc[e] = v;
    }
    if (lane == 0){
        #pragma unroll
        for (int e = 0; e < NE; e++) out_logits[(size_t)t*NE + e] = acc[e];
        int e0 = 0; float v0 = acc[0];
        #pragma unroll
        for (int e = 1; e < NE; e++) if (acc[e] > v0){ v0 = acc[e]; e0 = e; }
        int e1 = -1; float v1 = -3.4e38f;
        #pragma unroll
        for (int e = 0; e < NE; e++) if (e != e0 && acc[e] > v1){ v1 = acc[e]; e1 = e; }
        float ex = expf(v1 - v0);
        float s  = 1.0f + ex;
        float w0 = 1.0f / s, w1 = ex / s;
        int r0 = atomicAdd(&g_cnt[e0], 1);
        int r1 = atomicAdd(&g_cnt[e1], 1);
        g_as_e[2*t] = e0;   g_as_r[2*t] = r0;   g_as_w[2*t] = w0;
        g_as_e[2*t+1] = e1; g_as_r[2*t+1] = r1; g_as_w[2*t+1] = w1;
    }
}

// ---- launch 3: offsets + tile map + scatter (single block) ----
__global__ void k_offscat(){
    __shared__ int soff[NE+1];
    if (threadIdx.x == 0){
        int o = 0; soff[0] = 0;
        for (int e = 0; e < NE; e++){ o += (g_cnt[e] + 127) & ~127; soff[e+1] = o; }
    }
    __syncthreads();
    for (int i = threadIdx.x; i < NTILES; i += blockDim.x){
        int pos = i * 128, te = -1;
        for (int e = 0; e < NE; e++)
            if (pos >= soff[e] && pos < soff[e+1]) te = e;
        g_tile_e[i] = te;
    }
    if (threadIdx.x <= NE) g_off[threadIdx.x] = soff[threadIdx.x];
    for (int i = threadIdx.x; i < NASN; i += blockDim.x){
        int e = g_as_e[i];
        int pos = soff[e] + g_as_r[i];
        g_extok[pos] = i >> 1;
        g_tokpos[i] = pos;
    }
}

// ---- launches 4/5: pipelined fp16 GEMM (R14 config + ldmatrix A fragments) ----
// 128 thr, 4 warps (2x2), warp tile 64x64, BK=64 halves, 3-stage cp.async (96KB).
// FIRST: A = gather g_xp rows (K=512h), B = g_w1p, C = g_hp (gelu->f16 pairs)
// !FIRST: A = g_hp rows (K=2048h),      B = g_w2p, C = g_ybuf (fp32)
template<bool FIRST>
__global__ __launch_bounds__(128)
void k_gemm(){
    constexpr int KP  = FIRST ? (DM/2) : (DH/2);   // A row stride in u32 pairs
    constexpr int NT  = FIRST ? DH : DM;
    constexpr int NIT = FIRST ? (DM/64) : (DH/64); // 8 / 32 iters
    extern __shared__ uint32_t smem[];   // A: 3*4096 u32, B: 3*4096 u32 (96KB)
    int tile = blockIdx.y;
    int e = g_tile_e[tile];
    if (e < 0) return;
    int n0 = blockIdx.x * 128;
    int tid = threadIdx.x, lane = tid & 31, wid = tid >> 5;
    int g = lane >> 2, t4 = lane & 3;
    int wm = wid & 1, wn = wid >> 1;
    uint32_t smem_b;
    asm("{ .reg .u64 t; cvta.to.shared.u64 t, %1; cvt.u32.u64 %0, t; }"
        : "=r"(smem_b) : "l"(smem));

    const uint32_t* __restrict__ Wp = (FIRST ? g_w1p : g_w2p) + (size_t)e * KP * NT;
    const uint32_t* __restrict__ Ab = FIRST ? g_xp : (g_hp + (size_t)tile * 128 * KP);

    int tokr[8];
    if (FIRST){
        #pragma unroll
        for (int i = 0; i < 8; i++)
            tokr[i] = g_extok[tile*128 + (tid >> 3) + i*16];
    }
    int rA0 = tid >> 3, jA = tid & 7;     // A staging: row, 16B-chunk
    int rB0 = tid >> 5, cB = tid & 31;    // B staging: pair-row, 16B-chunk

    // stage `idx` covers pair-cols [idx*32, idx*32+32)
    auto issue = [&](int s, int idx){
        uint32_t ab = smem_b + s * 16384;
        uint32_t bb = smem_b + 49152 + s * 16384;
        int kp = idx * 32;
        #pragma unroll
        for (int i = 0; i < 8; i++){
            int r = rA0 + i*16;
            uint32_t dst = ab + ((r*32 + ((jA ^ (r & 7)) << 2)) << 2);
            const uint32_t* src; int sz = 16;
            if (FIRST){
                int tok = tokr[i];
                src = Ab + (size_t)(tok < 0 ? 0 : tok) * KP + kp + (jA << 2);
                sz = (tok < 0) ? 0 : 16;
            } else {
                src = Ab + (size_t)r * KP + kp + (jA << 2);
            }
            asm volatile("cp.async.cg.shared.global [%0], [%1], 16, %2;"
                         :: "r"(dst), "l"(src), "r"(sz));
        }
        #pragma unroll
        for (int i = 0; i < 8; i++){
            int r = rB0 + i*4;
            uint32_t dst = bb + ((r*128 + ((cB ^ ((r & 3) << 1)) << 2)) << 2);
            const uint32_t* src = Wp + (size_t)(kp + r) * NT + n0 + (cB << 2);
            asm volatile("cp.async.cg.shared.global [%0], [%1], 16, %2;"
                         :: "r"(dst), "l"(src), "r"(16));
        }
    };

    float acc[4][8][4];
    #pragma unroll
    for (int im = 0; im < 4; im++)
        #pragma unroll
        for (int jn = 0; jn < 8; jn++)
            #pragma unroll
            for (int q = 0; q < 4; q++) acc[im][jn][q] = 0.f;

    issue(0, 0); asm volatile("cp.async.commit_group;" ::: "memory");
    issue(1, 1); asm volatile("cp.async.commit_group;" ::: "memory");

    int bco[8];
    #pragma unroll
    for (int jn = 0; jn < 8; jn++){
        int c = wn*64 + jn*8 + g;
        bco[jn] = (((c >> 2) ^ (t4 << 1)) << 2) + (c & 3);
    }

    // ldmatrix A addressing: lane L supplies the row for matrix m = L>>3.
    // matrices per (im,ks): m0=(rb,cc0) m1=(rb+8,cc0) m2=(rb,cc1) m3=(rb+8,cc1),
    // rb = wm*64+im*16, cc = chunk 2ks+cc. Row r's chunk c lives at c^(r&7).
    int lo = lane & 7;                      // row-within-8 (= r&7 since rb mult of 8)
    int hi = lane >> 4;                     // cc = m>>1
    uint32_t aRow = (uint32_t)((wm*64 + ((lane >> 3) & 1)*8 + lo) * 128);  // bytes
    uint32_t cOffA[4];
    #pragma unroll
    for (int ks = 0; ks < 4; ks++)
        cOffA[ks] = (uint32_t)(((2*ks + hi) ^ lo) << 4);

    for (int it = 0; it < NIT; ++it){
        asm volatile("cp.async.wait_group 1;" ::: "memory");
        __syncthreads();
        if (it + 2 < NIT) issue((it + 2) % 3, it + 2);
        asm volatile("cp.async.commit_group;" ::: "memory");
        uint32_t abase = smem_b + (it % 3) * 16384;
        const uint32_t* sb = smem + 12288 + (it % 3) * 4096;
        #pragma unroll
        for (int ks = 0; ks < 4; ks++){
            int kk = ks * 8;
            uint32_t a[4][4];
            #pragma unroll
            for (int im = 0; im < 4; im++)
                ldsm4(a[im], abase + aRow + (uint32_t)(im*2048) + cOffA[ks]);
            uint32_t b[8][2];
            const uint32_t* sbr = sb + (kk + t4) * 128;
            #pragma unroll
            for (int jn = 0; jn < 8; jn++){
                b[jn][0] = sbr[bco[jn]];
                b[jn][1] = sbr[bco[jn] + 512];          // +4 pair-rows (= +8 halves)
            }
            #pragma unroll
            for (int im = 0; im < 4; im++)
                #pragma unroll
                for (int jn = 0; jn < 8; jn++)
                    mma16(acc[im][jn], a[im], b[jn]);
        }
    }

    // epilogue
    #pragma unroll
    for (int im = 0; im < 4; im++){
        int r = wm*64 + im*16 + g;
        #pragma unroll
        for (int jn = 0; jn < 8; jn++){
            int c = n0 + wn*64 + jn*8 + (t4 << 1);   // even
            if (FIRST){
                uint32_t* Ch = g_hp + (size_t)tile * 128 * (DH/2);
                int cp = c >> 1;
                Ch[(size_t)r * (DH/2) + cp] =
                    pk(gelu_exact(acc[im][jn][0]), gelu_exact(acc[im][jn][1]));
                Ch[(size_t)(r + 8) * (DH/2) + cp] =
                    pk(gelu_exact(acc[im][jn][2]), gelu_exact(acc[im][jn][3]));
            } else {
                float* Cf = g_ybuf + (size_t)tile * 128 * DM;
                *(float2*)(Cf + (size_t)r * DM + c)       = make_float2(acc[im][jn][0], acc[im][jn][1]);
                *(float2*)(Cf + (size_t)(r + 8) * DM + c) = make_float2(acc[im][jn][2], acc[im][jn][3]);
            }
        }
    }
}

// ---- launch 6: combine ----
__global__ void k_combine(float* __restrict__ out){
    int idx = blockIdx.x * 256 + threadIdx.x;
    int t = idx >> 7, d4 = idx & 127;
    int p0 = g_tokpos[2*t], p1 = g_tokpos[2*t + 1];
    float w0 = g_as_w[2*t], w1 = g_as_w[2*t + 1];
    float4 y0 = *(const float4*)(g_ybuf + (size_t)p0*DM + d4*4);
    float4 y1 = *(const float4*)(g_ybuf + (size_t)p1*DM + d4*4);
    float4 o;
    o.x = w0*y0.x + w1*y1.x;
    o.y = w0*y0.y + w1*y1.y;
    o.z = w0*y0.z + w1*y1.z;
    o.w = w0*y0.w + w1*y1.w;
    *(float4*)(out + (size_t)t*DM + d4*4) = o;
}

extern "C" void kernel_launch(void* const* d_in, const int* in_sizes, int n_in,
                              void* d_out, int out_size){
    const float* x  = (const float*)d_in[0];   // [16384, 512]
    const float* Wg = (const float*)d_in[1];   // [8, 512]
    const float* W1 = (const float*)d_in[2];   // [8, 512, 2048]
    const float* W2 = (const float*)d_in[3];   // [8, 2048, 512]
    float* out = (float*)d_out;                // out [T,512] then logits [T,8]

    const int SMEM = 98304;
    cudaFuncSetAttribute(k_gemm<true>,  cudaFuncAttributeMaxDynamicSharedMemorySize, SMEM);
    cudaFuncSetAttribute(k_gemm<false>, cudaFuncAttributeMaxDynamicSharedMemorySize, SMEM);

    k_initcvt<<<4096, 256>>>(W1, W2);                        // launch 1
    k_router<<<NTOK/8, 256>>>(x, Wg, out + (size_t)NTOK*DM); // launch 2 (+x cvt)
    k_offscat<<<1, 1024>>>();                                // launch 3
    k_gemm<true><<<dim3(DH/128, NTILES), 128, SMEM>>>();     // launch 4 <- ncu lands here
    k_gemm<false><<<dim3(DM/128, NTILES), 128, SMEM>>>();    // launch 5
    k_combine<<<(NTOK*128)/256, 256>>>(out);                 // launch 6
}